// round 2
// baseline (speedup 1.0000x reference)
#include <cuda_runtime.h>
#include <cuda_bf16.h>
#include <math.h>

// Problem constants
#define B_    4
#define NTOK  8192
#define DIM_  512
#define H_    8
#define DHEAD 64
#define WS_   256
#define NW    32
#define G_    32
#define KKEEP 179

__device__ __constant__ float c_dummy; // keep compiler honest

static __device__ float g_q[(size_t)B_ * H_ * NW * WS_ * DHEAD];     // 64MB
static __device__ float g_k[(size_t)B_ * H_ * NW * WS_ * DHEAD];     // 64MB
static __device__ float g_v[(size_t)B_ * H_ * NW * WS_ * DHEAD];     // 64MB
static __device__ float g_att[(size_t)B_ * NTOK * DIM_];             // 64MB
static __device__ float g_qmean[(size_t)B_ * H_ * WS_ * DHEAD];      // 2MB
static __device__ float g_kmean[(size_t)B_ * H_ * WS_ * DHEAD];      // 2MB
static __device__ float g_gbias[(size_t)B_ * H_ * WS_];              // 32KB

#define SCALE 0.04419417382415922f   // 512^-0.5

// ---------------------------------------------------------------------------
// Kernel 1: qkv = x @ w_qkv, scattered into windowed q/k/v layout
// M=32768, K=512, N=1536. BM=BN=64, BK=16, 256 threads, 4x4 per thread.
// ---------------------------------------------------------------------------
__global__ __launch_bounds__(256) void gemm_qkv_kernel(
    const float* __restrict__ A, const float* __restrict__ Bm)
{
    __shared__ float As[16][64];
    __shared__ float Bs[16][64];
    const int K = 512, N = 1536;
    const int bm = blockIdx.y * 64, bn = blockIdx.x * 64;
    const int tid = threadIdx.x;
    const int lrow = tid >> 2, lc4 = (tid & 3) << 2;   // A loader
    const int brow = tid >> 4, bc4 = (tid & 15) << 2;  // B loader
    const int ty = tid >> 4, tx = tid & 15;
    float acc[4][4] = {};

    const float* Aptr = A + (size_t)(bm + lrow) * K + lc4;
    const float* Bptr = Bm + (size_t)brow * N + bn + bc4;

    for (int k0 = 0; k0 < K; k0 += 16) {
        float4 a = *(const float4*)(Aptr + k0);
        As[lc4 + 0][lrow] = a.x; As[lc4 + 1][lrow] = a.y;
        As[lc4 + 2][lrow] = a.z; As[lc4 + 3][lrow] = a.w;
        *(float4*)&Bs[brow][bc4] = *(const float4*)(Bptr + (size_t)k0 * N);
        __syncthreads();
#pragma unroll
        for (int kk = 0; kk < 16; kk++) {
            float4 av = *(const float4*)&As[kk][ty << 2];
            float4 bv = *(const float4*)&Bs[kk][tx << 2];
            float aa[4] = {av.x, av.y, av.z, av.w};
            float bb[4] = {bv.x, bv.y, bv.z, bv.w};
#pragma unroll
            for (int i = 0; i < 4; i++)
#pragma unroll
                for (int j = 0; j < 4; j++) acc[i][j] += aa[i] * bb[j];
        }
        __syncthreads();
    }

    // Scatter: block spans exactly one of {q,k,v} and one head (bn % 64 == 0).
    const int part = bn / 512;
    const int head = (bn % 512) >> 6;
    float* dst = (part == 0) ? g_q : (part == 1) ? g_k : g_v;
#pragma unroll
    for (int i = 0; i < 4; i++) {
        int m = bm + (ty << 2) + i;
        int b = m >> 13, tok = m & 8191;
        int ww = tok >> 8, t = tok & 255;
        size_t base = ((((size_t)(b * H_ + head) * NW + ww) * WS_ + t) * DHEAD) + (tx << 2);
        float4 o = {acc[i][0], acc[i][1], acc[i][2], acc[i][3]};
        *(float4*)&dst[base] = o;
    }
}

// ---------------------------------------------------------------------------
// Kernel 2: q_mean / k_mean over windows
// ---------------------------------------------------------------------------
__global__ __launch_bounds__(256) void mean_kernel()
{
    int idx = blockIdx.x * 256 + threadIdx.x;   // < 524288 = B*H*WS*DHEAD
    size_t inner = (size_t)(idx & 16383);       // t*64+d
    size_t base = (size_t)(idx >> 14) * ((size_t)NW * 16384) + inner;
    float sq = 0.f, sk = 0.f;
#pragma unroll
    for (int w = 0; w < NW; w++) {
        sq += g_q[base + (size_t)w * 16384];
        sk += g_k[base + (size_t)w * 16384];
    }
    g_qmean[idx] = sq * (1.f / 32.f);
    g_kmean[idx] = sk * (1.f / 32.f);
}

// ---------------------------------------------------------------------------
// Kernel 3: global bias. One block per (b,h).
// gq[g,d] = sum_n gp[h,g,n]*qmean[n,d];  bias[m] = mean_g sum_d gq[g,d]*kmean[m,d]*scale
// ---------------------------------------------------------------------------
#define GLOB_SMEM_FLOATS (256 * 65 + 32 * 64)
__global__ __launch_bounds__(256) void global_kernel(const float* __restrict__ gp)
{
    extern __shared__ float sm[];
    float* km = sm;              // [256][65]
    float* gq = sm + 256 * 65;   // [32][64]
    const int bh = blockIdx.x;
    const int h = bh & 7;
    const int tid = threadIdx.x;
    const float* kmg = g_kmean + (size_t)bh * 16384;
    const float* qmg = g_qmean + (size_t)bh * 16384;

    for (int i = tid; i < 4096; i += 256) {
        int e = i * 4;
        float4 v = *(const float4*)(kmg + e);
        int t = e >> 6, d = e & 63;
        km[t * 65 + d + 0] = v.x; km[t * 65 + d + 1] = v.y;
        km[t * 65 + d + 2] = v.z; km[t * 65 + d + 3] = v.w;
    }
#pragma unroll
    for (int p = 0; p < 8; p++) {
        int pair = p * 256 + tid;        // g*64+d
        int g = pair >> 6, d = pair & 63;
        const float* gprow = gp + ((size_t)h * G_ + g) * WS_;
        float s = 0.f;
        for (int n = 0; n < 256; n++) s += gprow[n] * qmg[n * 64 + d];
        gq[pair] = s;
    }
    __syncthreads();

    int m = tid;
    float bias = 0.f;
    for (int g = 0; g < 32; g++) {
        float s = 0.f;
#pragma unroll
        for (int d = 0; d < 64; d++) s += gq[g * 64 + d] * km[m * 65 + d];
        bias += s;
    }
    g_gbias[(size_t)bh * 256 + m] = bias * SCALE * (1.f / 32.f);
}

// ---------------------------------------------------------------------------
// Kernel 4: fused windowed attention. Block = 64 query rows of one (b,h,w).
// scores -> +bias -> exact top-179 threshold (binary search on uint keys)
// -> softmax (unnormalized) -> PV -> scale by 1/sum -> write [b,n,dim] layout
// ---------------------------------------------------------------------------
#define KST 260   // K-transposed smem stride (float4 aligned, conflict-light)
#define QST 68
#define SST 260
#define ATTN_SMEM_FLOATS (64 * KST + 64 * QST + 256 * 64 + 64 * SST + 64)

__global__ __launch_bounds__(256) void attn_kernel(
    const float* __restrict__ lb, const float* __restrict__ gate)
{
    extern __shared__ float sm[];
    float* KsT    = sm;                         // [64][KST]  K^T: [d][t]
    float* QsT    = KsT + 64 * KST;             // [64][QST]  Q^T: [d][r]
    float* Vs     = QsT + 64 * QST;             // [256][64]  V:   [t][d]
    float* S      = Vs + 256 * 64;              // [64][SST]
    float* rowinv = S + 64 * SST;               // [64]

    const int tid = threadIdx.x;
    const int chunk = blockIdx.x;     // 0..3 (row chunk)
    const int ww = blockIdx.y;        // 0..31
    const int bh = blockIdx.z;        // 0..31
    const int h = bh & 7;
    const size_t win = ((size_t)bh * NW + ww) * (WS_ * DHEAD);
    const int row0 = chunk * 64;

    for (int i = tid; i < 4096; i += 256) {
        int e = i * 4;
        int t = e >> 6, d = e & 63;
        float4 kv = *(const float4*)(g_k + win + e);
        KsT[(d + 0) * KST + t] = kv.x; KsT[(d + 1) * KST + t] = kv.y;
        KsT[(d + 2) * KST + t] = kv.z; KsT[(d + 3) * KST + t] = kv.w;
        *(float4*)&Vs[e] = *(const float4*)(g_v + win + e);
    }
    for (int i = tid; i < 1024; i += 256) {
        int e = i * 4;
        int t = e >> 6, d = e & 63;
        float4 qv = *(const float4*)(g_q + win + (size_t)row0 * 64 + e);
        QsT[(d + 0) * QST + t] = qv.x; QsT[(d + 1) * QST + t] = qv.y;
        QsT[(d + 2) * QST + t] = qv.z; QsT[(d + 3) * QST + t] = qv.w;
    }
    __syncthreads();

    const float gate_s = 1.f / (1.f + __expf(-__ldg(gate + h)));
    const int ty = tid >> 4, tx = tid & 15;
    const float* gb = g_gbias + (size_t)bh * 256;

    // ---- scores: S = Q K^T * scale + local_bias + gate * global_bias ----
    for (int cb = 0; cb < 4; cb++) {
        float acc[4][4] = {};
#pragma unroll
        for (int kk = 0; kk < 64; kk++) {
            float4 q4 = *(const float4*)&QsT[kk * QST + (ty << 2)];
            float4 k4 = *(const float4*)&KsT[kk * KST + cb * 64 + (tx << 2)];
            float qa[4] = {q4.x, q4.y, q4.z, q4.w};
            float ka[4] = {k4.x, k4.y, k4.z, k4.w};
#pragma unroll
            for (int i = 0; i < 4; i++)
#pragma unroll
                for (int j = 0; j < 4; j++) acc[i][j] += qa[i] * ka[j];
        }
#pragma unroll
        for (int i = 0; i < 4; i++) {
            int r = (ty << 2) + i;
            int c0 = cb * 64 + (tx << 2);
            const float* lbrow = lb + ((size_t)h * WS_ + row0 + r) * WS_ + c0;
            float4 o;
            o.x = acc[i][0] * SCALE + lbrow[0] + gate_s * __ldg(gb + c0 + 0);
            o.y = acc[i][1] * SCALE + lbrow[1] + gate_s * __ldg(gb + c0 + 1);
            o.z = acc[i][2] * SCALE + lbrow[2] + gate_s * __ldg(gb + c0 + 2);
            o.w = acc[i][3] * SCALE + lbrow[3] + gate_s * __ldg(gb + c0 + 3);
            *(float4*)&S[r * SST + c0] = o;
        }
    }
    __syncthreads();

    // ---- per-row exact top-KKEEP threshold + unnormalized softmax ----
    const int warp = tid >> 5, lane = tid & 31;
    for (int rr = 0; rr < 8; rr++) {
        int r = warp * 8 + rr;
        float vals[8];
        unsigned keys[8];
#pragma unroll
        for (int q = 0; q < 8; q++) {
            float f = S[r * SST + q * 32 + lane];
            vals[q] = f;
            unsigned u = __float_as_uint(f);
            keys[q] = (u & 0x80000000u) ? ~u : (u | 0x80000000u);
        }
        // binary search for exact 179th-largest key: count(>=lo) >= 179, count(>=lo+1) < 179
        unsigned lo = 0u, hi = 0xFFFFFFFFu;
        for (int it = 0; it < 32; it++) {
            unsigned mid = lo + ((hi - lo) >> 1);
            int c = 0;
#pragma unroll
            for (int q = 0; q < 8; q++) c += (keys[q] >= mid) ? 1 : 0;
            c = __reduce_add_sync(0xffffffffu, c);
            if (c >= KKEEP) lo = mid; else hi = mid;
        }
        // row max via key order (max is always kept)
        unsigned mk = 0u;
#pragma unroll
        for (int q = 0; q < 8; q++) mk = max(mk, keys[q]);
        mk = __reduce_max_sync(0xffffffffu, mk);
        float mx = (mk & 0x80000000u) ? __uint_as_float(mk ^ 0x80000000u)
                                      : __uint_as_float(~mk);
        float ssum = 0.f;
#pragma unroll
        for (int q = 0; q < 8; q++) {
            float p = (keys[q] >= lo) ? __expf(vals[q] - mx) : 0.f;
            S[r * SST + q * 32 + lane] = p;
            ssum += p;
        }
#pragma unroll
        for (int o = 16; o > 0; o >>= 1) ssum += __shfl_xor_sync(0xffffffffu, ssum, o);
        if (lane == 0) rowinv[r] = 1.f / ssum;
    }
    __syncthreads();

    // ---- PV: out[64][64] = P[64][256] @ V[256][64], fold in 1/sum ----
    float acc[4][4] = {};
    for (int kk = 0; kk < 256; kk++) {
        float p0 = S[((ty << 2) + 0) * SST + kk];
        float p1 = S[((ty << 2) + 1) * SST + kk];
        float p2 = S[((ty << 2) + 2) * SST + kk];
        float p3 = S[((ty << 2) + 3) * SST + kk];
        float4 v4 = *(const float4*)&Vs[kk * 64 + (tx << 2)];
        float vv[4] = {v4.x, v4.y, v4.z, v4.w};
#pragma unroll
        for (int j = 0; j < 4; j++) {
            acc[0][j] += p0 * vv[j];
            acc[1][j] += p1 * vv[j];
            acc[2][j] += p2 * vv[j];
            acc[3][j] += p3 * vv[j];
        }
    }
    const int b = bh >> 3;
#pragma unroll
    for (int i = 0; i < 4; i++) {
        int r = (ty << 2) + i;
        float inv = rowinv[r];
        int tok = ww * 256 + row0 + r;
        size_t o = ((size_t)b * NTOK + tok) * DIM_ + h * 64 + (tx << 2);
        float4 ov = {acc[i][0] * inv, acc[i][1] * inv, acc[i][2] * inv, acc[i][3] * inv};
        *(float4*)&g_att[o] = ov;
    }
}

// ---------------------------------------------------------------------------
// Kernel 5: out = att @ w_out + b_out.  M=32768, K=512, N=512.
// ---------------------------------------------------------------------------
__global__ __launch_bounds__(256) void gemm_out_kernel(
    const float* __restrict__ Bm, const float* __restrict__ bias,
    float* __restrict__ out)
{
    __shared__ float As[16][64];
    __shared__ float Bs[16][64];
    const int K = 512, N = 512;
    const int bm = blockIdx.y * 64, bn = blockIdx.x * 64;
    const int tid = threadIdx.x;
    const int lrow = tid >> 2, lc4 = (tid & 3) << 2;
    const int brow = tid >> 4, bc4 = (tid & 15) << 2;
    const int ty = tid >> 4, tx = tid & 15;
    float acc[4][4] = {};

    const float* Aptr = g_att + (size_t)(bm + lrow) * K + lc4;
    const float* Bptr = Bm + (size_t)brow * N + bn + bc4;

    for (int k0 = 0; k0 < K; k0 += 16) {
        float4 a = *(const float4*)(Aptr + k0);
        As[lc4 + 0][lrow] = a.x; As[lc4 + 1][lrow] = a.y;
        As[lc4 + 2][lrow] = a.z; As[lc4 + 3][lrow] = a.w;
        *(float4*)&Bs[brow][bc4] = *(const float4*)(Bptr + (size_t)k0 * N);
        __syncthreads();
#pragma unroll
        for (int kk = 0; kk < 16; kk++) {
            float4 av = *(const float4*)&As[kk][ty << 2];
            float4 bv = *(const float4*)&Bs[kk][tx << 2];
            float aa[4] = {av.x, av.y, av.z, av.w};
            float bb[4] = {bv.x, bv.y, bv.z, bv.w};
#pragma unroll
            for (int i = 0; i < 4; i++)
#pragma unroll
                for (int j = 0; j < 4; j++) acc[i][j] += aa[i] * bb[j];
        }
        __syncthreads();
    }

    float4 bv = *(const float4*)(bias + bn + (tx << 2));
#pragma unroll
    for (int i = 0; i < 4; i++) {
        int m = bm + (ty << 2) + i;
        float4 o = {acc[i][0] + bv.x, acc[i][1] + bv.y,
                    acc[i][2] + bv.z, acc[i][3] + bv.w};
        *(float4*)&out[(size_t)m * N + bn + (tx << 2)] = o;
    }
}

// ---------------------------------------------------------------------------
extern "C" void kernel_launch(void* const* d_in, const int* in_sizes, int n_in,
                              void* d_out, int out_size)
{
    const float* x     = (const float*)d_in[0];
    const float* w_qkv = (const float*)d_in[1];
    const float* w_out = (const float*)d_in[2];
    const float* b_out = (const float*)d_in[3];
    const float* lb    = (const float*)d_in[4];
    const float* gp    = (const float*)d_in[5];
    const float* gate  = (const float*)d_in[6];
    float* out = (float*)d_out;

    const int glob_smem = GLOB_SMEM_FLOATS * 4;
    const int attn_smem = ATTN_SMEM_FLOATS * 4;
    cudaFuncSetAttribute(global_kernel, cudaFuncAttributeMaxDynamicSharedMemorySize, glob_smem);
    cudaFuncSetAttribute(attn_kernel, cudaFuncAttributeMaxDynamicSharedMemorySize, attn_smem);

    dim3 g1(1536 / 64, 32768 / 64);
    gemm_qkv_kernel<<<g1, 256>>>(x, w_qkv);

    mean_kernel<<<(B_ * H_ * WS_ * DHEAD) / 256, 256>>>();

    global_kernel<<<B_ * H_, 256, glob_smem>>>(gp);

    dim3 g4(4, NW, B_ * H_);
    attn_kernel<<<g4, 256, attn_smem>>>(lb, gate);

    dim3 g5(512 / 64, 32768 / 64);
    gemm_out_kernel<<<g5, 256>>>(w_out, b_out, out);
}

// round 4
// speedup vs baseline: 1.2686x; 1.2686x over previous
#include <cuda_runtime.h>
#include <cuda_bf16.h>
#include <math.h>

// Problem constants
#define B_    4
#define NTOK  8192
#define DIM_  512
#define H_    8
#define DHEAD 64
#define WS_   256
#define NW    32
#define G_    32
#define KKEEP 179

static __device__ float g_q[(size_t)B_ * H_ * NW * WS_ * DHEAD];     // 64MB
static __device__ float g_k[(size_t)B_ * H_ * NW * WS_ * DHEAD];     // 64MB
static __device__ float g_v[(size_t)B_ * H_ * NW * WS_ * DHEAD];     // 64MB
static __device__ float g_att[(size_t)B_ * NTOK * DIM_];             // 64MB
static __device__ float g_qmean[(size_t)B_ * H_ * WS_ * DHEAD];      // 2MB
static __device__ float g_kmean[(size_t)B_ * H_ * WS_ * DHEAD];      // 2MB
static __device__ float g_gbias[(size_t)B_ * H_ * WS_];              // 32KB

#define SCALE 0.04419417382415922f   // 512^-0.5

// ---------------------------------------------------------------------------
// tf32 helpers
// ---------------------------------------------------------------------------
__device__ __forceinline__ float f2tf_f(float x) {
    unsigned r;
    asm("cvt.rna.tf32.f32 %0, %1;" : "=r"(r) : "f"(x));
    return __uint_as_float(r);
}

__device__ __forceinline__ void mma8(float c[4],
    unsigned a0, unsigned a1, unsigned a2, unsigned a3,
    unsigned b0, unsigned b1)
{
    asm volatile(
        "mma.sync.aligned.m16n8k8.row.col.f32.tf32.tf32.f32 "
        "{%0,%1,%2,%3},{%4,%5,%6,%7},{%8,%9},{%0,%1,%2,%3};"
        : "+f"(c[0]), "+f"(c[1]), "+f"(c[2]), "+f"(c[3])
        : "r"(a0), "r"(a1), "r"(a2), "r"(a3), "r"(b0), "r"(b1));
}

// ---------------------------------------------------------------------------
// 3xTF32 GEMM: C[M,N] = A[M,K] @ B[K,N]. BM=BN=128, BK=16, 256 thr.
// Split a = a_hi + a_lo (tf32 each); c += ahi*bhi + ahi*blo + alo*bhi.
// EPI 0: qkv scatter into g_q/g_k/g_v windowed layout (A = x, B = w_qkv)
// EPI 1: out = g_att @ w_out + bias  (A param ignored, reads g_att)
// ---------------------------------------------------------------------------
#define SMSTR 136
#define TILE_F (16 * SMSTR)
#define GEMM_SMEM_FLOATS (8 * TILE_F)   // {A,B} x {hi,lo} x 2 buffers

template<int EPI>
__global__ __launch_bounds__(256) void gemm_tf32_kernel(
    const float* __restrict__ A, const float* __restrict__ Bm,
    const float* __restrict__ bias, float* __restrict__ Cout,
    int N, int K)
{
    extern __shared__ float smg[];
    float* AsHi = smg;                 // [2][16][SMSTR]
    float* AsLo = smg + 2 * TILE_F;
    float* BsHi = smg + 4 * TILE_F;
    float* BsLo = smg + 6 * TILE_F;

    const int bm = blockIdx.y * 128, bn = blockIdx.x * 128;
    const int tid = threadIdx.x, lane = tid & 31, warp = tid >> 5;
    const int wm = warp >> 2, wn = warp & 3;   // 2 x 4 warp grid

    const float* Ap = (EPI == 0) ? A : g_att;

    // loader mapping
    const int rowA = tid >> 2;                 // 0..63  (+64 for 2nd slot)
    const int kqA  = (tid & 3) << 2;           // 0,4,8,12
    const int krB  = tid >> 5;                 // 0..7   (+8 for 2nd slot)
    const int nqB  = (tid & 31) << 2;          // 0..124

    float c_[4][4][4] = {};

    auto stageA = [&](int buf, float4 v, int row, int kq) {
        float* hi = AsHi + buf * TILE_F;
        float* lo = AsLo + buf * TILE_F;
        float e[4] = {v.x, v.y, v.z, v.w};
#pragma unroll
        for (int j = 0; j < 4; j++) {
            float h = f2tf_f(e[j]);
            hi[(kq + j) * SMSTR + row] = h;
            lo[(kq + j) * SMSTR + row] = f2tf_f(e[j] - h);
        }
    };
    auto stageB = [&](int buf, float4 v, int kr, int nq) {
        float* hi = BsHi + buf * TILE_F + kr * SMSTR + nq;
        float* lo = BsLo + buf * TILE_F + kr * SMSTR + nq;
        float e[4] = {v.x, v.y, v.z, v.w};
        float hh[4], ll[4];
#pragma unroll
        for (int j = 0; j < 4; j++) {
            hh[j] = f2tf_f(e[j]);
            ll[j] = f2tf_f(e[j] - hh[j]);
        }
        *(float4*)hi = make_float4(hh[0], hh[1], hh[2], hh[3]);
        *(float4*)lo = make_float4(ll[0], ll[1], ll[2], ll[3]);
    };

    // ---- prologue: stage k-tile 0 into buffer 0 ----
    stageA(0, *(const float4*)(Ap + (size_t)(bm + rowA) * K + kqA), rowA, kqA);
    stageA(0, *(const float4*)(Ap + (size_t)(bm + rowA + 64) * K + kqA), rowA + 64, kqA);
    stageB(0, *(const float4*)(Bm + (size_t)krB * N + bn + nqB), krB, nqB);
    stageB(0, *(const float4*)(Bm + (size_t)(krB + 8) * N + bn + nqB), krB + 8, nqB);
    __syncthreads();

    int buf = 0;
    for (int k0 = 16; k0 <= K; k0 += 16) {
        const bool nxt = k0 < K;
        float4 na0, na1, nb0, nb1;
        if (nxt) {
            na0 = *(const float4*)(Ap + (size_t)(bm + rowA) * K + k0 + kqA);
            na1 = *(const float4*)(Ap + (size_t)(bm + rowA + 64) * K + k0 + kqA);
            nb0 = *(const float4*)(Bm + (size_t)(k0 + krB) * N + bn + nqB);
            nb1 = *(const float4*)(Bm + (size_t)(k0 + krB + 8) * N + bn + nqB);
        }

        const float* aH = AsHi + buf * TILE_F;
        const float* aL = AsLo + buf * TILE_F;
        const float* bH = BsHi + buf * TILE_F;
        const float* bL = BsLo + buf * TILE_F;

#pragma unroll
        for (int ks = 0; ks < 2; ks++) {
            const int kb = ks * 8 + (lane & 3);
            unsigned ah[4][4], al[4][4], bh[4][2], bl[4][2];
#pragma unroll
            for (int mi = 0; mi < 4; mi++) {
                int m = wm * 64 + mi * 16 + (lane >> 2);
                ah[mi][0] = __float_as_uint(aH[kb * SMSTR + m]);
                ah[mi][1] = __float_as_uint(aH[kb * SMSTR + m + 8]);
                ah[mi][2] = __float_as_uint(aH[(kb + 4) * SMSTR + m]);
                ah[mi][3] = __float_as_uint(aH[(kb + 4) * SMSTR + m + 8]);
                al[mi][0] = __float_as_uint(aL[kb * SMSTR + m]);
                al[mi][1] = __float_as_uint(aL[kb * SMSTR + m + 8]);
                al[mi][2] = __float_as_uint(aL[(kb + 4) * SMSTR + m]);
                al[mi][3] = __float_as_uint(aL[(kb + 4) * SMSTR + m + 8]);
            }
#pragma unroll
            for (int nj = 0; nj < 4; nj++) {
                int n = wn * 32 + nj * 8 + (lane >> 2);
                bh[nj][0] = __float_as_uint(bH[kb * SMSTR + n]);
                bh[nj][1] = __float_as_uint(bH[(kb + 4) * SMSTR + n]);
                bl[nj][0] = __float_as_uint(bL[kb * SMSTR + n]);
                bl[nj][1] = __float_as_uint(bL[(kb + 4) * SMSTR + n]);
            }
#pragma unroll
            for (int mi = 0; mi < 4; mi++)
#pragma unroll
                for (int nj = 0; nj < 4; nj++) {
                    mma8(c_[mi][nj], ah[mi][0], ah[mi][1], ah[mi][2], ah[mi][3],
                         bl[nj][0], bl[nj][1]);
                    mma8(c_[mi][nj], al[mi][0], al[mi][1], al[mi][2], al[mi][3],
                         bh[nj][0], bh[nj][1]);
                    mma8(c_[mi][nj], ah[mi][0], ah[mi][1], ah[mi][2], ah[mi][3],
                         bh[nj][0], bh[nj][1]);
                }
        }

        if (nxt) {
            const int nb = buf ^ 1;
            stageA(nb, na0, rowA, kqA);
            stageA(nb, na1, rowA + 64, kqA);
            stageB(nb, nb0, krB, nqB);
            stageB(nb, nb1, krB + 8, nqB);
        }
        __syncthreads();
        buf ^= 1;
    }

    // ---- epilogue ----
    if (EPI == 0) {
        const int part = bn >> 9;
        float* dst = (part == 0) ? g_q : (part == 1) ? g_k : g_v;
#pragma unroll
        for (int mi = 0; mi < 4; mi++) {
            int mbase = bm + wm * 64 + mi * 16 + (lane >> 2);
#pragma unroll
            for (int nj = 0; nj < 4; nj++) {
                int n = bn + wn * 32 + nj * 8 + ((lane & 3) << 1);
                int head = (n >> 6) & 7, d = n & 63;
#pragma unroll
                for (int half = 0; half < 2; half++) {
                    int m = mbase + half * 8;
                    int b = m >> 13, tok = m & 8191;
                    int w = tok >> 8, t = tok & 255;
                    size_t o = ((((size_t)(b * H_ + head) * NW + w) * WS_ + t) * DHEAD) + d;
                    *(float2*)&dst[o] =
                        make_float2(c_[mi][nj][half * 2], c_[mi][nj][half * 2 + 1]);
                }
            }
        }
    } else {
#pragma unroll
        for (int mi = 0; mi < 4; mi++) {
            int mbase = bm + wm * 64 + mi * 16 + (lane >> 2);
#pragma unroll
            for (int nj = 0; nj < 4; nj++) {
                int n = bn + wn * 32 + nj * 8 + ((lane & 3) << 1);
                float bx = bias[n], by = bias[n + 1];
#pragma unroll
                for (int half = 0; half < 2; half++) {
                    int m = mbase + half * 8;
                    *(float2*)&Cout[(size_t)m * N + n] =
                        make_float2(c_[mi][nj][half * 2] + bx,
                                    c_[mi][nj][half * 2 + 1] + by);
                }
            }
        }
    }
}

// ---------------------------------------------------------------------------
// Kernel 2: q_mean / k_mean over windows
// ---------------------------------------------------------------------------
__global__ __launch_bounds__(256) void mean_kernel()
{
    int idx = blockIdx.x * 256 + threadIdx.x;   // < 524288 = B*H*WS*DHEAD
    size_t inner = (size_t)(idx & 16383);       // t*64+d
    size_t base = (size_t)(idx >> 14) * ((size_t)NW * 16384) + inner;
    float sq = 0.f, sk = 0.f;
#pragma unroll
    for (int w = 0; w < NW; w++) {
        sq += g_q[base + (size_t)w * 16384];
        sk += g_k[base + (size_t)w * 16384];
    }
    g_qmean[idx] = sq * (1.f / 32.f);
    g_kmean[idx] = sk * (1.f / 32.f);
}

// ---------------------------------------------------------------------------
// Kernel 3: global bias. One block per (b,h).
// ---------------------------------------------------------------------------
#define GLOB_SMEM_FLOATS (256 * 65 + 32 * 64)
__global__ __launch_bounds__(256) void global_kernel(const float* __restrict__ gp)
{
    extern __shared__ float sm[];
    float* km = sm;              // [256][65]
    float* gq = sm + 256 * 65;   // [32][64]
    const int bh = blockIdx.x;
    const int h = bh & 7;
    const int tid = threadIdx.x;
    const float* kmg = g_kmean + (size_t)bh * 16384;
    const float* qmg = g_qmean + (size_t)bh * 16384;

    for (int i = tid; i < 4096; i += 256) {
        int e = i * 4;
        float4 v = *(const float4*)(kmg + e);
        int t = e >> 6, d = e & 63;
        km[t * 65 + d + 0] = v.x; km[t * 65 + d + 1] = v.y;
        km[t * 65 + d + 2] = v.z; km[t * 65 + d + 3] = v.w;
    }
#pragma unroll
    for (int p = 0; p < 8; p++) {
        int pair = p * 256 + tid;        // g*64+d
        int g = pair >> 6, d = pair & 63;
        const float* gprow = gp + ((size_t)h * G_ + g) * WS_;
        float s = 0.f;
        for (int n = 0; n < 256; n++) s += gprow[n] * qmg[n * 64 + d];
        gq[pair] = s;
    }
    __syncthreads();

    int m = tid;
    float bias = 0.f;
    for (int g = 0; g < 32; g++) {
        float s = 0.f;
#pragma unroll
        for (int d = 0; d < 64; d++) s += gq[g * 64 + d] * km[m * 65 + d];
        bias += s;
    }
    g_gbias[(size_t)bh * 256 + m] = bias * SCALE * (1.f / 32.f);
}

// ---------------------------------------------------------------------------
// Kernel 4: fused windowed attention (unchanged from passing R1 version).
// ---------------------------------------------------------------------------
#define KST 260
#define QST 68
#define SST 260
#define ATTN_SMEM_FLOATS (64 * KST + 64 * QST + 256 * 64 + 64 * SST + 64)

__global__ __launch_bounds__(256) void attn_kernel(
    const float* __restrict__ lb, const float* __restrict__ gate)
{
    extern __shared__ float sm[];
    float* KsT    = sm;                         // [64][KST]  K^T: [d][t]
    float* QsT    = KsT + 64 * KST;             // [64][QST]  Q^T: [d][r]
    float* Vs     = QsT + 64 * QST;             // [256][64]  V:   [t][d]
    float* S      = Vs + 256 * 64;              // [64][SST]
    float* rowinv = S + 64 * SST;               // [64]

    const int tid = threadIdx.x;
    const int chunk = blockIdx.x;     // 0..3
    const int ww = blockIdx.y;        // 0..31
    const int bh = blockIdx.z;        // 0..31
    const int h = bh & 7;
    const size_t win = ((size_t)bh * NW + ww) * (WS_ * DHEAD);
    const int row0 = chunk * 64;

    for (int i = tid; i < 4096; i += 256) {
        int e = i * 4;
        int t = e >> 6, d = e & 63;
        float4 kv = *(const float4*)(g_k + win + e);
        KsT[(d + 0) * KST + t] = kv.x; KsT[(d + 1) * KST + t] = kv.y;
        KsT[(d + 2) * KST + t] = kv.z; KsT[(d + 3) * KST + t] = kv.w;
        *(float4*)&Vs[e] = *(const float4*)(g_v + win + e);
    }
    for (int i = tid; i < 1024; i += 256) {
        int e = i * 4;
        int t = e >> 6, d = e & 63;
        float4 qv = *(const float4*)(g_q + win + (size_t)row0 * 64 + e);
        QsT[(d + 0) * QST + t] = qv.x; QsT[(d + 1) * QST + t] = qv.y;
        QsT[(d + 2) * QST + t] = qv.z; QsT[(d + 3) * QST + t] = qv.w;
    }
    __syncthreads();

    const float gate_s = 1.f / (1.f + __expf(-__ldg(gate + h)));
    const int ty = tid >> 4, tx = tid & 15;
    const float* gb = g_gbias + (size_t)bh * 256;

    for (int cb = 0; cb < 4; cb++) {
        float acc[4][4] = {};
#pragma unroll
        for (int kk = 0; kk < 64; kk++) {
            float4 q4 = *(const float4*)&QsT[kk * QST + (ty << 2)];
            float4 k4 = *(const float4*)&KsT[kk * KST + cb * 64 + (tx << 2)];
            float qa[4] = {q4.x, q4.y, q4.z, q4.w};
            float ka[4] = {k4.x, k4.y, k4.z, k4.w};
#pragma unroll
            for (int i = 0; i < 4; i++)
#pragma unroll
                for (int j = 0; j < 4; j++) acc[i][j] += qa[i] * ka[j];
        }
#pragma unroll
        for (int i = 0; i < 4; i++) {
            int r = (ty << 2) + i;
            int c0 = cb * 64 + (tx << 2);
            const float* lbrow = lb + ((size_t)h * WS_ + row0 + r) * WS_ + c0;
            float4 o;
            o.x = acc[i][0] * SCALE + lbrow[0] + gate_s * __ldg(gb + c0 + 0);
            o.y = acc[i][1] * SCALE + lbrow[1] + gate_s * __ldg(gb + c0 + 1);
            o.z = acc[i][2] * SCALE + lbrow[2] + gate_s * __ldg(gb + c0 + 2);
            o.w = acc[i][3] * SCALE + lbrow[3] + gate_s * __ldg(gb + c0 + 3);
            *(float4*)&S[r * SST + c0] = o;
        }
    }
    __syncthreads();

    const int warp = tid >> 5, lane = tid & 31;
    for (int rr = 0; rr < 8; rr++) {
        int r = warp * 8 + rr;
        float vals[8];
        unsigned keys[8];
#pragma unroll
        for (int q = 0; q < 8; q++) {
            float f = S[r * SST + q * 32 + lane];
            vals[q] = f;
            unsigned u = __float_as_uint(f);
            keys[q] = (u & 0x80000000u) ? ~u : (u | 0x80000000u);
        }
        unsigned lo = 0u, hi = 0xFFFFFFFFu;
        for (int it = 0; it < 32; it++) {
            unsigned mid = lo + ((hi - lo) >> 1);
            int c = 0;
#pragma unroll
            for (int q = 0; q < 8; q++) c += (keys[q] >= mid) ? 1 : 0;
            c = __reduce_add_sync(0xffffffffu, c);
            if (c >= KKEEP) lo = mid; else hi = mid;
        }
        unsigned mk = 0u;
#pragma unroll
        for (int q = 0; q < 8; q++) mk = max(mk, keys[q]);
        mk = __reduce_max_sync(0xffffffffu, mk);
        float mx = (mk & 0x80000000u) ? __uint_as_float(mk ^ 0x80000000u)
                                      : __uint_as_float(~mk);
        float ssum = 0.f;
#pragma unroll
        for (int q = 0; q < 8; q++) {
            float p = (keys[q] >= lo) ? __expf(vals[q] - mx) : 0.f;
            S[r * SST + q * 32 + lane] = p;
            ssum += p;
        }
#pragma unroll
        for (int o = 16; o > 0; o >>= 1) ssum += __shfl_xor_sync(0xffffffffu, ssum, o);
        if (lane == 0) rowinv[r] = 1.f / ssum;
    }
    __syncthreads();

    float acc[4][4] = {};
    for (int kk = 0; kk < 256; kk++) {
        float p0 = S[((ty << 2) + 0) * SST + kk];
        float p1 = S[((ty << 2) + 1) * SST + kk];
        float p2 = S[((ty << 2) + 2) * SST + kk];
        float p3 = S[((ty << 2) + 3) * SST + kk];
        float4 v4 = *(const float4*)&Vs[kk * 64 + (tx << 2)];
        float vv[4] = {v4.x, v4.y, v4.z, v4.w};
#pragma unroll
        for (int j = 0; j < 4; j++) {
            acc[0][j] += p0 * vv[j];
            acc[1][j] += p1 * vv[j];
            acc[2][j] += p2 * vv[j];
            acc[3][j] += p3 * vv[j];
        }
    }
    const int b = bh >> 3;
#pragma unroll
    for (int i = 0; i < 4; i++) {
        int r = (ty << 2) + i;
        float inv = rowinv[r];
        int tok = ww * 256 + row0 + r;
        size_t o = ((size_t)b * NTOK + tok) * DIM_ + h * 64 + (tx << 2);
        float4 ov = {acc[i][0] * inv, acc[i][1] * inv, acc[i][2] * inv, acc[i][3] * inv};
        *(float4*)&g_att[o] = ov;
    }
}

// ---------------------------------------------------------------------------
extern "C" void kernel_launch(void* const* d_in, const int* in_sizes, int n_in,
                              void* d_out, int out_size)
{
    const float* x     = (const float*)d_in[0];
    const float* w_qkv = (const float*)d_in[1];
    const float* w_out = (const float*)d_in[2];
    const float* b_out = (const float*)d_in[3];
    const float* lb    = (const float*)d_in[4];
    const float* gp    = (const float*)d_in[5];
    const float* gate  = (const float*)d_in[6];
    float* out = (float*)d_out;

    const int glob_smem = GLOB_SMEM_FLOATS * 4;
    const int attn_smem = ATTN_SMEM_FLOATS * 4;
    const int gemm_smem = GEMM_SMEM_FLOATS * 4;
    cudaFuncSetAttribute(global_kernel, cudaFuncAttributeMaxDynamicSharedMemorySize, glob_smem);
    cudaFuncSetAttribute(attn_kernel, cudaFuncAttributeMaxDynamicSharedMemorySize, attn_smem);
    cudaFuncSetAttribute(gemm_tf32_kernel<0>, cudaFuncAttributeMaxDynamicSharedMemorySize, gemm_smem);
    cudaFuncSetAttribute(gemm_tf32_kernel<1>, cudaFuncAttributeMaxDynamicSharedMemorySize, gemm_smem);

    // qkv GEMM: M=32768, N=1536, K=512 (3xTF32 HMMA)
    dim3 g1(1536 / 128, 32768 / 128);
    gemm_tf32_kernel<0><<<g1, 256, gemm_smem>>>(x, w_qkv, nullptr, nullptr, 1536, 512);

    mean_kernel<<<(B_ * H_ * WS_ * DHEAD) / 256, 256>>>();

    global_kernel<<<B_ * H_, 256, glob_smem>>>(gp);

    dim3 g4(4, NW, B_ * H_);
    attn_kernel<<<g4, 256, attn_smem>>>(lb, gate);

    // out GEMM: M=32768, N=512, K=512 (3xTF32 HMMA)
    dim3 g5(512 / 128, 32768 / 128);
    gemm_tf32_kernel<1><<<g5, 256, gemm_smem>>>(nullptr, w_out, b_out, out, 512, 512);
}